// round 2
// baseline (speedup 1.0000x reference)
#include <cuda_runtime.h>
#include <math.h>

// Problem constants
#define TT    4096   // tokens = B*S
#define DIN   4096
#define DOUT  4096
#define NE    8
#define NRTR  64     // E * K_RTR
#define KEXT  272    // 256 (E*K_EXP) + 8 (w->bias) + 8 zero pad -> 17 * BK(16)

// Scratch (device globals; allocation is forbidden)
__device__ float g_gl[TT * NRTR];       // gate logits [T, 64]
__device__ float g_w[TT * NE];          // dense routed weights [T, 8]
__device__ float g_aext[TT * KEXT];     // [h' (scaled) | w | 0pad] per token
__device__ float g_bext[DOUT * KEXT];   // [u_flat | bias^T | 0pad] per out-col

// ---------------------------------------------------------------------------
// Build B-extension matrix: g_bext[n, k] = u[e][n][r] (k=e*32+r, k<256),
// expert_bias[e][n] (k=256+e), 0 (pad).
// ---------------------------------------------------------------------------
__global__ void bext_kernel(const float* __restrict__ u, const float* __restrict__ eb) {
    int idx = blockIdx.x * blockDim.x + threadIdx.x;
    if (idx >= DOUT * KEXT) return;
    int n = idx / KEXT;
    int k = idx - n * KEXT;
    float v = 0.f;
    if (k < 256) {
        int e = k >> 5, r = k & 31;
        v = u[(e * DOUT + n) * 32 + r];
    } else if (k < 264) {
        v = eb[(k - 256) * DOUT + n];
    }
    g_bext[idx] = v;
}

// ---------------------------------------------------------------------------
// Routing: L2 norm over K_RTR of gate logits -> softmax -> top2 -> renorm.
// Writes dense per-expert weights to g_w and to the w-slot of g_aext.
// ---------------------------------------------------------------------------
__global__ void routing_kernel() {
    int t = blockIdx.x * blockDim.x + threadIdx.x;
    if (t >= TT) return;
    float rl[NE];
    #pragma unroll
    for (int e = 0; e < NE; e++) {
        float s = 0.f;
        #pragma unroll
        for (int r = 0; r < 8; r++) {
            float v = g_gl[t * NRTR + e * 8 + r];
            s += v * v;
        }
        rl[e] = sqrtf(s);
    }
    int i1 = 0;
    #pragma unroll
    for (int e = 1; e < NE; e++) if (rl[e] > rl[i1]) i1 = e;
    int i2 = (i1 == 0) ? 1 : 0;
    #pragma unroll
    for (int e = 0; e < NE; e++) if (e != i1 && rl[e] > rl[i2]) i2 = e;
    // top2 weights renormalized: softmax monotone -> top2 of logits;
    // w1 = exp(r1)/(exp(r1)+exp(r2)), stable form:
    float e2 = expf(rl[i2] - rl[i1]);
    float inv = 1.f / (1.f + e2);
    float w1 = inv, w2 = e2 * inv;
    #pragma unroll
    for (int e = 0; e < NE; e++) {
        float v = (e == i1) ? w1 : ((e == i2) ? w2 : 0.f);
        g_w[t * NE + e] = v;
        g_aext[t * KEXT + 256 + e] = v;
    }
    #pragma unroll
    for (int p = 0; p < 8; p++) g_aext[t * KEXT + 264 + p] = 0.f;
}

// ---------------------------------------------------------------------------
// Generic NT-SGEMM: C[M,N] = A[M,K] * B[N,K]^T, K = DIN, double buffered.
// BM=128, BK=16, TM=8 fixed; 256 threads. MODE 0: store to g_gl (gate).
// MODE 1: scale by routed weight and store to g_aext (expert h').
// ---------------------------------------------------------------------------
template<int BN, int TN, int MODE>
__global__ __launch_bounds__(256) void sgemm128(const float* __restrict__ A,
                                                const float* __restrict__ B) {
    constexpr int BM = 128, BK = 16, TM = 8;
    constexpr int LA = BM + 4, LB = BN + 4;
    constexpr int BP = BN / 64;
    __shared__ float As[2][BK][LA];
    __shared__ float Bs[2][BK][LB];
    const int tid = threadIdx.x;
    const int tx = tid % (BN / TN);
    const int ty = tid / (BN / TN);
    const int arow = tid >> 2;
    const int acol = (tid & 3) * 4;

    const float* Ag = A + (blockIdx.y * BM + arow) * DIN + acol;
    const float* Bg = B + (blockIdx.x * BN + arow) * DIN + acol;

    float acc[TM][TN];
    #pragma unroll
    for (int i = 0; i < TM; i++)
        #pragma unroll
        for (int j = 0; j < TN; j++) acc[i][j] = 0.f;

    float4 av[2], bv[BP];

    auto sts = [&](int buf) {
        #pragma unroll
        for (int p = 0; p < 2; p++) {
            As[buf][acol + 0][arow + p * 64] = av[p].x;
            As[buf][acol + 1][arow + p * 64] = av[p].y;
            As[buf][acol + 2][arow + p * 64] = av[p].z;
            As[buf][acol + 3][arow + p * 64] = av[p].w;
        }
        #pragma unroll
        for (int p = 0; p < BP; p++) {
            Bs[buf][acol + 0][arow + p * 64] = bv[p].x;
            Bs[buf][acol + 1][arow + p * 64] = bv[p].y;
            Bs[buf][acol + 2][arow + p * 64] = bv[p].z;
            Bs[buf][acol + 3][arow + p * 64] = bv[p].w;
        }
    };

    #pragma unroll
    for (int p = 0; p < 2; p++)  av[p] = *(const float4*)(Ag + p * 64 * DIN);
    #pragma unroll
    for (int p = 0; p < BP; p++) bv[p] = *(const float4*)(Bg + p * 64 * DIN);
    sts(0);
    __syncthreads();

    const int nk = DIN / BK;
    for (int kt = 0; kt < nk; kt++) {
        const int cur = kt & 1;
        if (kt + 1 < nk) {
            #pragma unroll
            for (int p = 0; p < 2; p++)
                av[p] = *(const float4*)(Ag + (kt + 1) * BK + p * 64 * DIN);
            #pragma unroll
            for (int p = 0; p < BP; p++)
                bv[p] = *(const float4*)(Bg + (kt + 1) * BK + p * 64 * DIN);
        }
        #pragma unroll
        for (int kk = 0; kk < BK; kk++) {
            float a[TM], b[TN];
            #pragma unroll
            for (int i = 0; i < TM; i++) a[i] = As[cur][kk][ty * TM + i];
            #pragma unroll
            for (int j = 0; j < TN; j++) b[j] = Bs[cur][kk][tx * TN + j];
            #pragma unroll
            for (int i = 0; i < TM; i++)
                #pragma unroll
                for (int j = 0; j < TN; j++) acc[i][j] += a[i] * b[j];
        }
        if (kt + 1 < nk) {
            sts(cur ^ 1);
            __syncthreads();
        }
    }

    const int row0 = blockIdx.y * BM + ty * TM;
    const int col0 = blockIdx.x * BN + tx * TN;
    if (MODE == 0) {
        #pragma unroll
        for (int i = 0; i < TM; i++)
            #pragma unroll
            for (int j = 0; j < TN; j++)
                g_gl[(row0 + i) * NRTR + col0 + j] = acc[i][j];
    } else {
        const int e = col0 >> 5;  // TN=8 tile never crosses a 32-col expert block
        #pragma unroll
        for (int i = 0; i < TM; i++) {
            float wv = g_w[(row0 + i) * NE + e];
            #pragma unroll
            for (int j = 0; j < TN; j++)
                g_aext[(row0 + i) * KEXT + col0 + j] = acc[i][j] * wv;
        }
    }
}

// ---------------------------------------------------------------------------
// Main fused GEMM: out = x @ shared_w^T (K=4096, seg 0)
//                      + [h'|w|0] @ [u_flat|bias|0]^T (K=272, seg 1)
//                      + shared_b
// ---------------------------------------------------------------------------
__global__ __launch_bounds__(256) void main_gemm(const float* __restrict__ X,
                                                 const float* __restrict__ W,
                                                 const float* __restrict__ Bias,
                                                 float* __restrict__ C) {
    constexpr int BK = 16;
    constexpr int LA = 132, LB = 132;
    __shared__ float As[2][BK][LA];
    __shared__ float Bs[2][BK][LB];
    const int tid = threadIdx.x;
    const int tx = tid & 15, ty = tid >> 4;
    const int arow = tid >> 2;
    const int acol = (tid & 3) * 4;

    float acc[8][8];
    #pragma unroll
    for (int i = 0; i < 8; i++)
        #pragma unroll
        for (int j = 0; j < 8; j++) acc[i][j] = 0.f;

    float4 av[2], bv[2];
    auto sts = [&](int buf) {
        #pragma unroll
        for (int p = 0; p < 2; p++) {
            As[buf][acol + 0][arow + p * 64] = av[p].x;
            As[buf][acol + 1][arow + p * 64] = av[p].y;
            As[buf][acol + 2][arow + p * 64] = av[p].z;
            As[buf][acol + 3][arow + p * 64] = av[p].w;
            Bs[buf][acol + 0][arow + p * 64] = bv[p].x;
            Bs[buf][acol + 1][arow + p * 64] = bv[p].y;
            Bs[buf][acol + 2][arow + p * 64] = bv[p].z;
            Bs[buf][acol + 3][arow + p * 64] = bv[p].w;
        }
    };

    #pragma unroll 1
    for (int s = 0; s < 2; s++) {
        const float* Ag;
        const float* Bg;
        int ld, nk;
        if (s == 0) {
            Ag = X + (blockIdx.y * 128 + arow) * DIN + acol;
            Bg = W + (blockIdx.x * 128 + arow) * DIN + acol;
            ld = DIN; nk = DIN / BK;
        } else {
            Ag = g_aext + (blockIdx.y * 128 + arow) * KEXT + acol;
            Bg = g_bext + (blockIdx.x * 128 + arow) * KEXT + acol;
            ld = KEXT; nk = KEXT / BK;
        }
        av[0] = *(const float4*)(Ag);
        av[1] = *(const float4*)(Ag + 64 * ld);
        bv[0] = *(const float4*)(Bg);
        bv[1] = *(const float4*)(Bg + 64 * ld);
        __syncthreads();   // previous segment's last compute must finish before reuse
        sts(0);
        __syncthreads();

        for (int kt = 0; kt < nk; kt++) {
            const int cur = kt & 1;
            if (kt + 1 < nk) {
                av[0] = *(const float4*)(Ag + (kt + 1) * BK);
                av[1] = *(const float4*)(Ag + (kt + 1) * BK + 64 * ld);
                bv[0] = *(const float4*)(Bg + (kt + 1) * BK);
                bv[1] = *(const float4*)(Bg + (kt + 1) * BK + 64 * ld);
            }
            #pragma unroll
            for (int kk = 0; kk < BK; kk++) {
                float a[8], b[8];
                #pragma unroll
                for (int i = 0; i < 8; i++) a[i] = As[cur][kk][ty * 8 + i];
                #pragma unroll
                for (int j = 0; j < 8; j++) b[j] = Bs[cur][kk][tx * 8 + j];
                #pragma unroll
                for (int i = 0; i < 8; i++)
                    #pragma unroll
                    for (int j = 0; j < 8; j++) acc[i][j] += a[i] * b[j];
            }
            if (kt + 1 < nk) {
                sts(cur ^ 1);
                __syncthreads();
            }
        }
    }

    const int row0 = blockIdx.y * 128 + ty * 8;
    const int col0 = blockIdx.x * 128 + tx * 8;
    #pragma unroll
    for (int i = 0; i < 8; i++)
        #pragma unroll
        for (int j = 0; j < 8; j++)
            C[(row0 + i) * DOUT + col0 + j] = acc[i][j] + Bias[col0 + j];
}

// ---------------------------------------------------------------------------
extern "C" void kernel_launch(void* const* d_in, const int* in_sizes, int n_in,
                              void* d_out, int out_size) {
    const float* x    = (const float*)d_in[0];  // [T, 4096]
    const float* gate = (const float*)d_in[1];  // [64, 4096]
    const float* shw  = (const float*)d_in[2];  // [4096, 4096]
    const float* shb  = (const float*)d_in[3];  // [4096]
    const float* u    = (const float*)d_in[4];  // [8, 4096, 32]
    const float* svh  = (const float*)d_in[5];  // [8, 32, 4096] -> [256, 4096]
    const float* eb   = (const float*)d_in[6];  // [8, 4096]
    float* out = (float*)d_out;                 // [T, 4096]

    bext_kernel<<<(DOUT * KEXT + 255) / 256, 256>>>(u, eb);
    sgemm128<64, 4, 0><<<dim3(1, TT / 128), 256>>>(x, gate);            // gate logits
    routing_kernel<<<(TT + 255) / 256, 256>>>();                        // top2 weights
    sgemm128<128, 8, 1><<<dim3(256 / 128, TT / 128), 256>>>(x, svh);    // h' (scaled)
    main_gemm<<<dim3(DOUT / 128, TT / 128), 256>>>(x, shw, shb, out);   // fused output
}

// round 6
// speedup vs baseline: 1.0107x; 1.0107x over previous
#include <cuda_runtime.h>
#include <cstdint>
#include <math.h>

#define TT   4096
#define DIN  4096
#define DOUT 4096
#define KEXT 320          // 256 + 8 (w slots) + 56 pad = 10 chunks of 32

// ---------------- scratch (device globals; allocation forbidden) ----------
__device__ __align__(16) float g_rw[TT * 8];          // dense routed weights
__device__ __align__(16) float g_aext[TT * KEXT];     // [w*h | w | 0]
__device__ __align__(16) float g_bext[DOUT * KEXT];   // [u | bias | 0]
__device__ __align__(16) float g_exp[TT * DOUT];      // expert output

// ---------------- helpers ----------------
__device__ __forceinline__ uint32_t smem_u32(const void* p) {
    uint32_t a;
    asm("{ .reg .u64 t; cvta.to.shared.u64 t, %1; cvt.u32.u64 %0, t; }" : "=r"(a) : "l"(p));
    return a;
}
__device__ __forceinline__ void cpa16(uint32_t dst, const void* src) {
    asm volatile("cp.async.cg.shared.global [%0], [%1], 16;" :: "r"(dst), "l"(src));
}
__device__ __forceinline__ uint32_t f2tf32(float f) {
    uint32_t r;
    asm("cvt.rna.tf32.f32 %0, %1;" : "=r"(r) : "f"(f));
    return r;
}
__device__ __forceinline__ void mma8(float* c, const uint32_t* a, const uint32_t* b) {
    asm volatile(
        "mma.sync.aligned.m16n8k8.row.col.f32.tf32.tf32.f32 "
        "{%0,%1,%2,%3}, {%4,%5,%6,%7}, {%8,%9}, {%0,%1,%2,%3};"
        : "+f"(c[0]), "+f"(c[1]), "+f"(c[2]), "+f"(c[3])
        : "r"(a[0]), "r"(a[1]), "r"(a[2]), "r"(a[3]), "r"(b[0]), "r"(b[1]));
}

// ---------------------------------------------------------------------------
// Fused gate GEMM (exact fp32, full K) + routing. One block = 64 tokens.
// Writes routed weights to rw AND the w-slots + zero pad of aext rows.
// ---------------------------------------------------------------------------
__global__ __launch_bounds__(256) void gate_rout(const float* __restrict__ x,
                                                 const float* __restrict__ gate,
                                                 float* __restrict__ rw,
                                                 float* __restrict__ aext) {
    __shared__ float xs[64 * 68];
    __shared__ float gs[64 * 68];
    const int tid = threadIdx.x;
    const int t0 = blockIdx.x * 64;
    const int tr = tid >> 4, tc = tid & 15;

    float acc[4][4];
    #pragma unroll
    for (int i = 0; i < 4; i++)
        #pragma unroll
        for (int j = 0; j < 4; j++) acc[i][j] = 0.f;

    for (int kc = 0; kc < DIN; kc += 64) {
        __syncthreads();
        #pragma unroll
        for (int i = 0; i < 4; i++) {
            int vid = tid + i * 256;                 // 1024 float4 total
            int row = vid >> 4, kq = (vid & 15) * 4;
            *(float4*)(xs + row * 68 + kq) =
                *(const float4*)(x + (size_t)(t0 + row) * DIN + kc + kq);
            *(float4*)(gs + row * 68 + kq) =
                *(const float4*)(gate + (size_t)row * DIN + kc + kq);
        }
        __syncthreads();
        #pragma unroll
        for (int kk = 0; kk < 64; kk += 4) {
            float4 a4[4], b4[4];
            #pragma unroll
            for (int i = 0; i < 4; i++) a4[i] = *(float4*)(xs + (tr * 4 + i) * 68 + kk);
            #pragma unroll
            for (int j = 0; j < 4; j++) b4[j] = *(float4*)(gs + (tc * 4 + j) * 68 + kk);
            #pragma unroll
            for (int i = 0; i < 4; i++)
                #pragma unroll
                for (int j = 0; j < 4; j++) {
                    acc[i][j] += a4[i].x * b4[j].x + a4[i].y * b4[j].y;
                    acc[i][j] += a4[i].z * b4[j].z + a4[i].w * b4[j].w;
                }
        }
    }
    __syncthreads();
    // stash logits: gs[token][gate]
    #pragma unroll
    for (int i = 0; i < 4; i++)
        #pragma unroll
        for (int j = 0; j < 4; j++)
            gs[(tr * 4 + i) * 68 + tc * 4 + j] = acc[i][j];
    __syncthreads();

    if (tid < 64) {
        const int t = t0 + tid;
        float rl[8];
        #pragma unroll
        for (int e = 0; e < 8; e++) {
            float s = 0.f;
            #pragma unroll
            for (int r = 0; r < 8; r++) {
                float v = gs[tid * 68 + e * 8 + r];
                s += v * v;
            }
            rl[e] = sqrtf(s);
        }
        int i1 = 0;
        #pragma unroll
        for (int e = 1; e < 8; e++) if (rl[e] > rl[i1]) i1 = e;
        int i2 = (i1 == 0) ? 1 : 0;
        #pragma unroll
        for (int e = 0; e < 8; e++) if (e != i1 && rl[e] > rl[i2]) i2 = e;
        float e2 = expf(rl[i2] - rl[i1]);
        float inv = 1.f / (1.f + e2);
        #pragma unroll
        for (int e = 0; e < 8; e++) {
            float w = (e == i1) ? inv : ((e == i2) ? e2 * inv : 0.f);
            rw[t * 8 + e] = w;
            aext[(size_t)t * KEXT + 256 + e] = w;   // w slot (pairs with bias row in bext)
        }
        #pragma unroll
        for (int p = 0; p < 56; p++)
            aext[(size_t)t * KEXT + 264 + p] = 0.f; // pad
    }
}

// ---------------------------------------------------------------------------
// bext[n,k] = u[e][n][r] (k=e*32+r<256) | expert_bias[e][n] (k=256+e) | 0 pad
// ---------------------------------------------------------------------------
__global__ void bext_build(const float* __restrict__ u, const float* __restrict__ eb,
                           float* __restrict__ bext) {
    int i = blockIdx.x * blockDim.x + threadIdx.x;
    if (i >= DOUT * KEXT) return;
    int n = i / KEXT, k = i - n * KEXT;
    float v = 0.f;
    if (k < 256) { int e = k >> 5, r = k & 31; v = u[(e * DOUT + n) * 32 + r]; }
    else if (k < 264) v = eb[(k - 256) * DOUT + n];
    bext[i] = v;
}

// ---------------------------------------------------------------------------
// tf32 mma.sync GEMM (one fixed shape, proven): C[M,N] = A B^T.
// BM=256 BN=128 WM=WN=64, 8 warps, 2-stage cp.async, S=36 smem stride.
// wscale != 0: C = acc * wscale[row*8 + (col>>5)]        (expert-h mode)
// else:        C = acc + bias[col] + addsrc[row,col]     (plain mode)
// ---------------------------------------------------------------------------
#define BM 256
#define BN 128
#define SS 36
#define STAGE ((BM + BN) * SS)
#define SM_BYTES (2 * STAGE * 4)

__global__ __launch_bounds__(256, 1)
void tgemm(const float* __restrict__ A, const float* __restrict__ B,
           int lda, int ldb, int nch,
           float* __restrict__ C, int ldc,
           const float* __restrict__ bias, const float* __restrict__ addsrc,
           const float* __restrict__ wscale) {
    extern __shared__ __align__(16) float sm[];
    const int tid = threadIdx.x;
    const int m0 = blockIdx.y * BM, n0 = blockIdx.x * BN;

    auto load_stage = [&](int c, int buf) {
        const int kc0 = c * 32;
        float* sA = sm + buf * STAGE;
        float* sB = sA + BM * SS;
        #pragma unroll
        for (int i = 0; i < 8; i++) {                  // BM*8/256
            int idx = tid + i * 256;
            int m = idx >> 3, kc = (idx & 7) * 4;
            cpa16(smem_u32(sA + m * SS + kc), A + (size_t)(m0 + m) * lda + kc0 + kc);
        }
        #pragma unroll
        for (int i = 0; i < 4; i++) {                  // BN*8/256
            int idx = tid + i * 256;
            int nn = idx >> 3, kc = (idx & 7) * 4;
            cpa16(smem_u32(sB + nn * SS + kc), B + (size_t)(n0 + nn) * ldb + kc0 + kc);
        }
        asm volatile("cp.async.commit_group;" ::: "memory");
    };

    float acc[4][8][4];
    #pragma unroll
    for (int i = 0; i < 4; i++)
        #pragma unroll
        for (int j = 0; j < 8; j++)
            #pragma unroll
            for (int q = 0; q < 4; q++) acc[i][j][q] = 0.f;

    const int warp = tid >> 5, lane = tid & 31;
    const int qr = lane >> 2, qc = lane & 3;
    const int wm = warp >> 1, wn = warp & 1;           // 4x2 warp grid

    load_stage(0, 0);
    load_stage(1, 1);

    #pragma unroll 1
    for (int c = 0; c < nch; c++) {
        const int buf = c & 1;
        if (c + 1 < nch) asm volatile("cp.async.wait_group 1;" ::: "memory");
        else             asm volatile("cp.async.wait_group 0;" ::: "memory");
        __syncthreads();
        const float* sA = sm + buf * STAGE + (wm * 64 + qr) * SS + qc;
        const float* sB = sm + buf * STAGE + BM * SS + (wn * 64 + qr) * SS + qc;

        #pragma unroll
        for (int kk = 0; kk < 4; kk++) {
            uint32_t af[4][4], bf[8][2];
            #pragma unroll
            for (int mt = 0; mt < 4; mt++) {
                const float* p = sA + mt * 16 * SS + kk * 8;
                af[mt][0] = f2tf32(p[0]);
                af[mt][1] = f2tf32(p[8 * SS]);
                af[mt][2] = f2tf32(p[4]);
                af[mt][3] = f2tf32(p[8 * SS + 4]);
            }
            #pragma unroll
            for (int nt = 0; nt < 8; nt++) {
                const float* p = sB + nt * 8 * SS + kk * 8;
                bf[nt][0] = f2tf32(p[0]);
                bf[nt][1] = f2tf32(p[4]);
            }
            #pragma unroll
            for (int mt = 0; mt < 4; mt++)
                #pragma unroll
                for (int nt = 0; nt < 8; nt++)
                    mma8(acc[mt][nt], af[mt], bf[nt]);
        }
        __syncthreads();
        if (c + 2 < nch) load_stage(c + 2, buf);
    }

    const int rbase = m0 + wm * 64;
    const int cbase = n0 + wn * 64;
    #pragma unroll
    for (int mt = 0; mt < 4; mt++) {
        #pragma unroll
        for (int nt = 0; nt < 8; nt++) {
            const int r = rbase + mt * 16 + qr;
            const int col = cbase + nt * 8 + qc * 2;
            float2 v0 = make_float2(acc[mt][nt][0], acc[mt][nt][1]);
            float2 v1 = make_float2(acc[mt][nt][2], acc[mt][nt][3]);
            if (wscale) {
                const int e = col >> 5;                // col,col+1 in same 32-block
                float w0 = wscale[(size_t)r * 8 + e];
                float w1 = wscale[(size_t)(r + 8) * 8 + e];
                v0.x *= w0; v0.y *= w0;
                v1.x *= w1; v1.y *= w1;
            } else {
                if (bias) {
                    float bx = bias[col], by = bias[col + 1];
                    v0.x += bx; v0.y += by;
                    v1.x += bx; v1.y += by;
                }
                if (addsrc) {
                    float2 a0 = *(const float2*)(addsrc + (size_t)r * ldc + col);
                    float2 a1 = *(const float2*)(addsrc + (size_t)(r + 8) * ldc + col);
                    v0.x += a0.x; v0.y += a0.y;
                    v1.x += a1.x; v1.y += a1.y;
                }
            }
            *(float2*)(C + (size_t)r * ldc + col) = v0;
            *(float2*)(C + (size_t)(r + 8) * ldc + col) = v1;
        }
    }
}

// ---------------------------------------------------------------------------
extern "C" void kernel_launch(void* const* d_in, const int* in_sizes, int n_in,
                              void* d_out, int out_size) {
    const float* x    = (const float*)d_in[0];
    const float* gate = (const float*)d_in[1];
    const float* shw  = (const float*)d_in[2];
    const float* shb  = (const float*)d_in[3];
    const float* u    = (const float*)d_in[4];
    const float* svh  = (const float*)d_in[5];
    const float* eb   = (const float*)d_in[6];
    float* out = (float*)d_out;

    cudaFuncSetAttribute(tgemm, cudaFuncAttributeMaxDynamicSharedMemorySize, SM_BYTES);

    // 1) bext = [u | bias | 0]
    bext_build<<<(DOUT * KEXT + 255) / 256, 256>>>(u, eb, g_bext);

    // 2) gate GEMM (exact fp32) + routing; writes g_rw and aext w-slots/pad
    gate_rout<<<TT / 64, 256>>>(x, gate, g_rw, g_aext);

    // 3) aext[:,0:256) = w * (x @ svh^T)   (tf32, scaled epilogue)
    tgemm<<<dim3(256 / BN, TT / BM), 256, SM_BYTES>>>(
        x, svh, DIN, DIN, DIN / 32, g_aext, KEXT, nullptr, nullptr, g_rw);

    // 4) expert out = aext @ bext^T
    tgemm<<<dim3(DOUT / BN, TT / BM), 256, SM_BYTES>>>(
        g_aext, g_bext, KEXT, KEXT, KEXT / 32, g_exp, DOUT, nullptr, nullptr, nullptr);

    // 5) out = x @ shared_w^T + shared_b + expert
    tgemm<<<dim3(DOUT / BN, TT / BM), 256, SM_BYTES>>>(
        x, shw, DIN, DIN, DIN / 32, out, DOUT, shb, g_exp, nullptr);
}

// round 7
// speedup vs baseline: 1.1837x; 1.1712x over previous
#include <cuda_runtime.h>
#include <cstdint>
#include <math.h>

// Problem constants
#define TT    4096   // tokens = B*S
#define DIN   4096
#define DOUT  4096
#define NE    8
#define NRTR  64     // E * K_RTR
#define KEXT  272    // 256 (E*K_EXP) + 8 (w->bias) + 8 zero pad -> 17 * BK(16)

// Scratch (device globals; allocation is forbidden)
__device__ float g_gl[TT * NRTR];       // gate logits [T, 64]
__device__ float g_w[TT * NE];          // dense routed weights [T, 8]
__device__ float g_aext[TT * KEXT];     // [h' (scaled) | w | 0pad] per token
__device__ float g_bext[DOUT * KEXT];   // [u_flat | bias^T | 0pad] per out-col

// ---------------- f32x2 packed-FMA helpers (FFMA2 hardware path) ----------
__device__ __forceinline__ void fma2(uint64_t& d, uint64_t a, uint64_t b) {
    asm("fma.rn.f32x2 %0, %1, %2, %0;" : "+l"(d) : "l"(a), "l"(b));
}
__device__ __forceinline__ uint64_t dup32(float v) {
    uint64_t r;
    asm("mov.b64 %0, {%1, %1};" : "=l"(r) : "f"(v));
    return r;
}
__device__ __forceinline__ float2 unpk(uint64_t v) {
    float2 r;
    asm("mov.b64 {%0, %1}, %2;" : "=f"(r.x), "=f"(r.y) : "l"(v));
    return r;
}

// ---------------------------------------------------------------------------
// Build B-extension matrix: g_bext[n, k] = u[e][n][r] (k=e*32+r, k<256),
// expert_bias[e][n] (k=256+e), 0 (pad).
// ---------------------------------------------------------------------------
__global__ void bext_kernel(const float* __restrict__ u, const float* __restrict__ eb) {
    int idx = blockIdx.x * blockDim.x + threadIdx.x;
    if (idx >= DOUT * KEXT) return;
    int n = idx / KEXT;
    int k = idx - n * KEXT;
    float v = 0.f;
    if (k < 256) {
        int e = k >> 5, r = k & 31;
        v = u[(e * DOUT + n) * 32 + r];
    } else if (k < 264) {
        v = eb[(k - 256) * DOUT + n];
    }
    g_bext[idx] = v;
}

// ---------------------------------------------------------------------------
// Routing: L2 norm over K_RTR of gate logits -> softmax -> top2 -> renorm.
// ---------------------------------------------------------------------------
__global__ void routing_kernel() {
    int t = blockIdx.x * blockDim.x + threadIdx.x;
    if (t >= TT) return;
    float rl[NE];
    #pragma unroll
    for (int e = 0; e < NE; e++) {
        float s = 0.f;
        #pragma unroll
        for (int r = 0; r < 8; r++) {
            float v = g_gl[t * NRTR + e * 8 + r];
            s += v * v;
        }
        rl[e] = sqrtf(s);
    }
    int i1 = 0;
    #pragma unroll
    for (int e = 1; e < NE; e++) if (rl[e] > rl[i1]) i1 = e;
    int i2 = (i1 == 0) ? 1 : 0;
    #pragma unroll
    for (int e = 0; e < NE; e++) if (e != i1 && rl[e] > rl[i2]) i2 = e;
    float e2 = expf(rl[i2] - rl[i1]);
    float inv = 1.f / (1.f + e2);
    float w1 = inv, w2 = e2 * inv;
    #pragma unroll
    for (int e = 0; e < NE; e++) {
        float v = (e == i1) ? w1 : ((e == i2) ? w2 : 0.f);
        g_w[t * NE + e] = v;
        g_aext[t * KEXT + 256 + e] = v;
    }
    #pragma unroll
    for (int p = 0; p < 8; p++) g_aext[t * KEXT + 264 + p] = 0.f;
}

// ---------------------------------------------------------------------------
// Generic NT-SGEMM, f32x2 packed: C[M,N] = A[M,K] * B[N,K]^T, K = DIN.
// BK=16, double buffered, 256 threads = (BM/TM)*(BN/TN).
// MODE 0: store to g_gl (gate). MODE 1: scale by routed weight -> g_aext.
// ---------------------------------------------------------------------------
template<int BM, int BN, int TM, int TN, int MODE>
__global__ __launch_bounds__(256) void sgemm(const float* __restrict__ A,
                                             const float* __restrict__ B) {
    constexpr int BK = 16;
    constexpr int LA = BM + 4, LB = BN + 4;
    constexpr int AP = BM * 4 / 256;   // float4 loads per thread (A)
    constexpr int BP = BN * 4 / 256;
    constexpr int MH = TM / 2;
    __shared__ float As[2][BK][LA];
    __shared__ float Bs[2][BK][LB];
    const int tid = threadIdx.x;
    const int tx = tid % (BN / TN);
    const int ty = tid / (BN / TN);
    const int arow = tid >> 2;
    const int acol = (tid & 3) * 4;

    const float* Ag = A + (size_t)(blockIdx.y * BM + arow) * DIN + acol;
    const float* Bg = B + (size_t)(blockIdx.x * BN + arow) * DIN + acol;

    uint64_t acc[MH][TN];
    #pragma unroll
    for (int i = 0; i < MH; i++)
        #pragma unroll
        for (int j = 0; j < TN; j++) acc[i][j] = 0ull;

    float4 av[AP], bv[BP];

    auto sts = [&](int buf) {
        #pragma unroll
        for (int p = 0; p < AP; p++) {
            As[buf][acol + 0][arow + p * 64] = av[p].x;
            As[buf][acol + 1][arow + p * 64] = av[p].y;
            As[buf][acol + 2][arow + p * 64] = av[p].z;
            As[buf][acol + 3][arow + p * 64] = av[p].w;
        }
        #pragma unroll
        for (int p = 0; p < BP; p++) {
            Bs[buf][acol + 0][arow + p * 64] = bv[p].x;
            Bs[buf][acol + 1][arow + p * 64] = bv[p].y;
            Bs[buf][acol + 2][arow + p * 64] = bv[p].z;
            Bs[buf][acol + 3][arow + p * 64] = bv[p].w;
        }
    };

    #pragma unroll
    for (int p = 0; p < AP; p++) av[p] = *(const float4*)(Ag + (size_t)p * 64 * DIN);
    #pragma unroll
    for (int p = 0; p < BP; p++) bv[p] = *(const float4*)(Bg + (size_t)p * 64 * DIN);
    sts(0);
    __syncthreads();

    const int nk = DIN / BK;
    for (int kt = 0; kt < nk; kt++) {
        const int cur = kt & 1;
        if (kt + 1 < nk) {
            #pragma unroll
            for (int p = 0; p < AP; p++)
                av[p] = *(const float4*)(Ag + (kt + 1) * BK + (size_t)p * 64 * DIN);
            #pragma unroll
            for (int p = 0; p < BP; p++)
                bv[p] = *(const float4*)(Bg + (kt + 1) * BK + (size_t)p * 64 * DIN);
        }
        #pragma unroll
        for (int kk = 0; kk < BK; kk++) {
            uint64_t a2[MH], bd[TN];
            #pragma unroll
            for (int i = 0; i < MH; i++)
                a2[i] = *(const uint64_t*)&As[cur][kk][ty * TM + 2 * i];
            #pragma unroll
            for (int j = 0; j < TN; j++)
                bd[j] = dup32(Bs[cur][kk][tx * TN + j]);
            #pragma unroll
            for (int i = 0; i < MH; i++)
                #pragma unroll
                for (int j = 0; j < TN; j++)
                    fma2(acc[i][j], a2[i], bd[j]);
        }
        if (kt + 1 < nk) {
            sts(cur ^ 1);
            __syncthreads();
        }
    }

    const int row0 = blockIdx.y * BM + ty * TM;
    const int col0 = blockIdx.x * BN + tx * TN;
    if (MODE == 0) {
        #pragma unroll
        for (int i = 0; i < MH; i++)
            #pragma unroll
            for (int j = 0; j < TN; j++) {
                float2 v = unpk(acc[i][j]);
                g_gl[(size_t)(row0 + 2 * i) * NRTR + col0 + j] = v.x;
                g_gl[(size_t)(row0 + 2 * i + 1) * NRTR + col0 + j] = v.y;
            }
    } else {
        const int e = col0 >> 5;  // TN=8 tile never crosses a 32-col expert block
        #pragma unroll
        for (int i = 0; i < MH; i++) {
            float w0 = g_w[(size_t)(row0 + 2 * i) * NE + e];
            float w1 = g_w[(size_t)(row0 + 2 * i + 1) * NE + e];
            #pragma unroll
            for (int j = 0; j < TN; j++) {
                float2 v = unpk(acc[i][j]);
                g_aext[(size_t)(row0 + 2 * i) * KEXT + col0 + j] = v.x * w0;
                g_aext[(size_t)(row0 + 2 * i + 1) * KEXT + col0 + j] = v.y * w1;
            }
        }
    }
}

// ---------------------------------------------------------------------------
// Main fused GEMM (f32x2): out = x @ shared_w^T (K=4096, seg 0)
//                              + [h'|w|0] @ [u_flat|bias|0]^T (K=272, seg 1)
//                              + shared_b
// ---------------------------------------------------------------------------
__global__ __launch_bounds__(256) void main_gemm(const float* __restrict__ X,
                                                 const float* __restrict__ W,
                                                 const float* __restrict__ Bias,
                                                 float* __restrict__ C) {
    constexpr int BK = 16;
    constexpr int LA = 132, LB = 132;
    __shared__ float As[2][BK][LA];
    __shared__ float Bs[2][BK][LB];
    const int tid = threadIdx.x;
    const int tx = tid & 15, ty = tid >> 4;
    const int arow = tid >> 2;
    const int acol = (tid & 3) * 4;

    uint64_t acc[4][8];
    #pragma unroll
    for (int i = 0; i < 4; i++)
        #pragma unroll
        for (int j = 0; j < 8; j++) acc[i][j] = 0ull;

    float4 av[2], bv[2];
    auto sts = [&](int buf) {
        #pragma unroll
        for (int p = 0; p < 2; p++) {
            As[buf][acol + 0][arow + p * 64] = av[p].x;
            As[buf][acol + 1][arow + p * 64] = av[p].y;
            As[buf][acol + 2][arow + p * 64] = av[p].z;
            As[buf][acol + 3][arow + p * 64] = av[p].w;
            Bs[buf][acol + 0][arow + p * 64] = bv[p].x;
            Bs[buf][acol + 1][arow + p * 64] = bv[p].y;
            Bs[buf][acol + 2][arow + p * 64] = bv[p].z;
            Bs[buf][acol + 3][arow + p * 64] = bv[p].w;
        }
    };

    #pragma unroll 1
    for (int s = 0; s < 2; s++) {
        const float* Ag;
        const float* Bg;
        int ld, nk;
        if (s == 0) {
            Ag = X + (size_t)(blockIdx.y * 128 + arow) * DIN + acol;
            Bg = W + (size_t)(blockIdx.x * 128 + arow) * DIN + acol;
            ld = DIN; nk = DIN / BK;
        } else {
            Ag = g_aext + (size_t)(blockIdx.y * 128 + arow) * KEXT + acol;
            Bg = g_bext + (size_t)(blockIdx.x * 128 + arow) * KEXT + acol;
            ld = KEXT; nk = KEXT / BK;
        }
        av[0] = *(const float4*)(Ag);
        av[1] = *(const float4*)(Ag + (size_t)64 * ld);
        bv[0] = *(const float4*)(Bg);
        bv[1] = *(const float4*)(Bg + (size_t)64 * ld);
        __syncthreads();   // previous segment's last compute must finish before reuse
        sts(0);
        __syncthreads();

        for (int kt = 0; kt < nk; kt++) {
            const int cur = kt & 1;
            if (kt + 1 < nk) {
                av[0] = *(const float4*)(Ag + (kt + 1) * BK);
                av[1] = *(const float4*)(Ag + (kt + 1) * BK + (size_t)64 * ld);
                bv[0] = *(const float4*)(Bg + (kt + 1) * BK);
                bv[1] = *(const float4*)(Bg + (kt + 1) * BK + (size_t)64 * ld);
            }
            #pragma unroll
            for (int kk = 0; kk < BK; kk++) {
                uint64_t a2[4], bd[8];
                #pragma unroll
                for (int i = 0; i < 4; i++)
                    a2[i] = *(const uint64_t*)&As[cur][kk][ty * 8 + 2 * i];
                #pragma unroll
                for (int j = 0; j < 8; j++)
                    bd[j] = dup32(Bs[cur][kk][tx * 8 + j]);
                #pragma unroll
                for (int i = 0; i < 4; i++)
                    #pragma unroll
                    for (int j = 0; j < 8; j++)
                        fma2(acc[i][j], a2[i], bd[j]);
            }
            if (kt + 1 < nk) {
                sts(cur ^ 1);
                __syncthreads();
            }
        }
    }

    const int row0 = blockIdx.y * 128 + ty * 8;
    const int col0 = blockIdx.x * 128 + tx * 8;
    #pragma unroll
    for (int i = 0; i < 4; i++)
        #pragma unroll
        for (int j = 0; j < 8; j++) {
            float2 v = unpk(acc[i][j]);
            float b = Bias[col0 + j];
            C[(size_t)(row0 + 2 * i) * DOUT + col0 + j] = v.x + b;
            C[(size_t)(row0 + 2 * i + 1) * DOUT + col0 + j] = v.y + b;
        }
}

// ---------------------------------------------------------------------------
extern "C" void kernel_launch(void* const* d_in, const int* in_sizes, int n_in,
                              void* d_out, int out_size) {
    const float* x    = (const float*)d_in[0];  // [T, 4096]
    const float* gate = (const float*)d_in[1];  // [64, 4096]
    const float* shw  = (const float*)d_in[2];  // [4096, 4096]
    const float* shb  = (const float*)d_in[3];  // [4096]
    const float* u    = (const float*)d_in[4];  // [8, 4096, 32]
    const float* svh  = (const float*)d_in[5];  // [8, 32, 4096] -> [256, 4096]
    const float* eb   = (const float*)d_in[6];  // [8, 4096]
    float* out = (float*)d_out;                 // [T, 4096]

    bext_kernel<<<(DOUT * KEXT + 255) / 256, 256>>>(u, eb);
    sgemm<64, 64, 4, 4, 0><<<dim3(1, TT / 64), 256>>>(x, gate);          // gate logits
    routing_kernel<<<(TT + 255) / 256, 256>>>();                         // top2 weights
    sgemm<64, 128, 4, 8, 1><<<dim3(256 / 128, TT / 64), 256>>>(x, svh);  // h' (scaled)
    main_gemm<<<dim3(DOUT / 128, TT / 128), 256>>>(x, shw, shb, out);    // fused output
}